// round 13
// baseline (speedup 1.0000x reference)
#include <cuda_runtime.h>
#include <cuda_bf16.h>
#include <cstddef>
#include <cstdint>

#define NN    50000
#define EE    800000
#define DIN   256
#define DH    128
#define NL    1000
#define NLPAD 1024
#define NNPAD 50048          // 391 * 128
#define KC3   384            // 3 * 128
#define KC6   768            // 3 * 256

// ---------------- scratch (static device allocations; no cudaMalloc) -------
__device__ float g_h   [NN * DH];
__device__ float g_h2  [NN * DH];
__device__ float g_res [NN * DH];
__device__ int   g_rowptr[NN + 1];
__device__ int   g_cursor[NN];
__device__ int   g_perm  [EE];
__device__ int   g_srcp  [EE];
__device__ float g_wp    [EE];
__device__ float g_ws    [EE];
__device__ int   g_bsum  [64];
__device__ int   g_boff  [64];
__device__ __nv_bfloat16 g_acat[(size_t)NNPAD * KC6];    // A split (reused, stride 768 or 384)
__device__ __nv_bfloat16 g_bwin[DH * KC6];               // W_in split  [128][768]
__device__ __nv_bfloat16 g_bw1 [DH * KC3];               // W1 split    [128][384]
__device__ __nv_bfloat16 g_bw2 [DH * KC3];               // W2 split    [128][384]
__device__ __nv_bfloat16 g_bout[(size_t)NLPAD * KC3];    // W_out split [1024][384], tail 0

// ---------------- mma.sync / cp.async helpers (baseline PTX) ---------------
__device__ __forceinline__ uint32_t s2u(const void* p) {
    uint32_t a;
    asm("{ .reg .u64 t; cvta.to.shared.u64 t, %1; cvt.u32.u64 %0, t; }"
        : "=r"(a) : "l"(p));
    return a;
}
__device__ __forceinline__ void ldm_x4(uint32_t* d, uint32_t addr) {
    asm volatile("ldmatrix.sync.aligned.m8n8.x4.shared.b16 {%0,%1,%2,%3}, [%4];"
                 : "=r"(d[0]), "=r"(d[1]), "=r"(d[2]), "=r"(d[3]) : "r"(addr));
}
__device__ __forceinline__ void mma_bf16(float* c, const uint32_t* a, const uint32_t* b) {
    asm volatile(
        "mma.sync.aligned.m16n8k16.row.col.f32.bf16.bf16.f32 "
        "{%0,%1,%2,%3}, {%4,%5,%6,%7}, {%8,%9}, {%0,%1,%2,%3};"
        : "+f"(c[0]), "+f"(c[1]), "+f"(c[2]), "+f"(c[3])
        : "r"(a[0]), "r"(a[1]), "r"(a[2]), "r"(a[3]), "r"(b[0]), "r"(b[1]));
}
__device__ __forceinline__ void cpa16(uint32_t dst, const void* src) {
    asm volatile("cp.async.cg.shared.global [%0], [%1], 16;"
                 :: "r"(dst), "l"(src) : "memory");
}
__device__ __forceinline__ void cpa_commit() {
    asm volatile("cp.async.commit_group;" ::: "memory");
}
template <int N>
__device__ __forceinline__ void cpa_wait() {
    asm volatile("cp.async.wait_group %0;" :: "n"(N) : "memory");
}

// ---------------- CSR build kernels ----------------------------------------
__global__ void zero_cnt_kernel(int n) {
    int i = blockIdx.x * blockDim.x + threadIdx.x;
    if (i < n) g_cursor[i] = 0;
}

__global__ void hist_kernel(const int* __restrict__ dst, int e) {
    int i = blockIdx.x * blockDim.x + threadIdx.x;
    if (i < e) atomicAdd(&g_cursor[dst[i]], 1);
}

__global__ void scan1_kernel(int n) {
    __shared__ int sdata[1024];
    int tid = threadIdx.x;
    int i = blockIdx.x * 1024 + tid;
    int v = (i < n) ? g_cursor[i] : 0;
    sdata[tid] = v;
    __syncthreads();
    for (int off = 1; off < 1024; off <<= 1) {
        int t = (tid >= off) ? sdata[tid - off] : 0;
        __syncthreads();
        sdata[tid] += t;
        __syncthreads();
    }
    if (i < n) g_rowptr[i] = sdata[tid] - v;
    if (tid == 1023) g_bsum[blockIdx.x] = sdata[1023];
}

__global__ void scan2_kernel(int nb, int n) {
    if (threadIdx.x == 0) {
        int run = 0;
        for (int b = 0; b < nb; b++) { g_boff[b] = run; run += g_bsum[b]; }
        g_rowptr[n] = run;
    }
}

__global__ void scan3_kernel(int n) {
    int i = blockIdx.x * blockDim.x + threadIdx.x;
    if (i < n) {
        int v = g_rowptr[i] + g_boff[i >> 10];
        g_rowptr[i] = v;
        g_cursor[i] = v;
    }
}

__global__ void fill_kernel(const int* __restrict__ dst, int e) {
    int i = blockIdx.x * blockDim.x + threadIdx.x;
    if (i < e) {
        int d = dst[i];
        int p = atomicAdd(&g_cursor[d], 1);
        g_perm[p] = i;
    }
}

__global__ void segsort_kernel(int n) {
    int node = blockIdx.x * blockDim.x + threadIdx.x;
    if (node >= n) return;
    int b = g_rowptr[node], e = g_rowptr[node + 1];
    for (int i = b + 1; i < e; i++) {
        int key = g_perm[i];
        int j = i - 1;
        while (j >= b && g_perm[j] > key) { g_perm[j + 1] = g_perm[j]; j--; }
        g_perm[j + 1] = key;
    }
}

__global__ void permute_kernel(const int* __restrict__ src,
                               const float* __restrict__ ppi_w,
                               const float* __restrict__ self_w, int e) {
    int j = blockIdx.x * blockDim.x + threadIdx.x;
    if (j < e) {
        int ed = g_perm[j];
        g_srcp[j] = src[ed];
        g_wp[j]   = ppi_w[ed];
        g_ws[j]   = self_w[ed];
    }
}

// ---------------- split-store helper ----------------------------------------
union BF4 { __nv_bfloat16 b[4]; uint2 u; };

__device__ __forceinline__ void split4(const float4 v, BF4& hi, BF4& lo) {
    float f[4] = {v.x, v.y, v.z, v.w};
#pragma unroll
    for (int i = 0; i < 4; i++) {
        __nv_bfloat16 h = __float2bfloat16(f[i]);
        hi.b[i] = h;
        lo.b[i] = __float2bfloat16(f[i] - __bfloat162float(h));
    }
}

// ---------------- fused aggregation: writes res fp32 + agg split bf16 ------
// agg goes directly into g_acat as [hi|hi|lo] (stride KC3) for the next hgemm.
__global__ void agg_kernel(const float* __restrict__ h, int n) {
    int warp = (blockIdx.x * blockDim.x + threadIdx.x) >> 5;
    int lane = threadIdx.x & 31;
    if (warp >= n) return;
    int beg = g_rowptr[warp], end = g_rowptr[warp + 1];
    float4 ap = make_float4(0.f, 0.f, 0.f, 0.f);
    float4 as = make_float4(0.f, 0.f, 0.f, 0.f);
    for (int j = beg; j < end; j++) {
        int   s  = g_srcp[j];
        float wp = g_wp[j];
        float ws = g_ws[j];
        const float4 v = *(const float4*)&h[(size_t)s * DH + lane * 4];
        ap.x += wp * v.x; ap.y += wp * v.y; ap.z += wp * v.z; ap.w += wp * v.w;
        as.x += ws * v.x; as.y += ws * v.y; as.z += ws * v.z; as.w += ws * v.w;
    }
    *(float4*)&g_res[(size_t)warp * DH + lane * 4] = as;
    BF4 hi, lo;
    split4(ap, hi, lo);
    size_t base = (size_t)warp * KC3 + lane * 4;
    *(uint2*)&g_acat[base]       = hi.u;
    *(uint2*)&g_acat[base + 128] = hi.u;
    *(uint2*)&g_acat[base + 256] = lo.u;
}

// ---------------- split-prep kernels ----------------------------------------
// x (fp32 [NN][256]) -> g_acat [hi|hi|lo] stride 768
__global__ void xsplit_kernel(const float* __restrict__ x) {
    int idx = blockIdx.x * blockDim.x + threadIdx.x;
    if (idx >= NN * (DIN / 4)) return;
    int m = idx / (DIN / 4), k4 = (idx % (DIN / 4)) * 4;
    float4 v = *(const float4*)&x[(size_t)m * DIN + k4];
    BF4 hi, lo;
    split4(v, hi, lo);
    size_t base = (size_t)m * KC6 + k4;
    *(uint2*)&g_acat[base]       = hi.u;
    *(uint2*)&g_acat[base + 256] = hi.u;
    *(uint2*)&g_acat[base + 512] = lo.u;
}

// h (fp32 [NN][128]) -> g_acat [hi|hi|lo] stride 384
__global__ void hsplit_kernel(const float* __restrict__ h) {
    int idx = blockIdx.x * blockDim.x + threadIdx.x;
    if (idx >= NN * (DH / 4)) return;
    int m = idx / (DH / 4), k4 = (idx % (DH / 4)) * 4;
    float4 v = *(const float4*)&h[(size_t)m * DH + k4];
    BF4 hi, lo;
    split4(v, hi, lo);
    size_t base = (size_t)m * KC3 + k4;
    *(uint2*)&g_acat[base]       = hi.u;
    *(uint2*)&g_acat[base + 128] = hi.u;
    *(uint2*)&g_acat[base + 256] = lo.u;
}

// W [K][Nw] row-major -> bcat[n][3K] = [hi|lo|hi]
__global__ void wsplit_kernel(const float* __restrict__ W, __nv_bfloat16* bcat,
                              int K, int Nw) {
    int idx = blockIdx.x * blockDim.x + threadIdx.x;
    if (idx >= Nw * K) return;
    int n = idx / K, k = idx % K;
    float v = W[(size_t)k * Nw + n];
    __nv_bfloat16 hi = __float2bfloat16(v);
    __nv_bfloat16 lo = __float2bfloat16(v - __bfloat162float(hi));
    size_t base = (size_t)n * (3 * K);
    bcat[base + k]         = hi;
    bcat[base + K + k]     = lo;
    bcat[base + 2 * K + k] = hi;
}

// ---------------- unified HMMA GEMM -----------------------------------------
// C[M,Nc] = epi(Acat[M,KC] @ Bcat[NcPad,KC]^T + bias)
// mode 0: relu   mode 1: relu + res   mode 2: plain (out layer)
// CTA 128x128, 8 warps (4 M x 2 N), warp tile 32x64, cp.async double buffer.
#define HG_BM 128
#define HG_BN 128
#define HG_BK 64

__global__ void __launch_bounds__(256, 2) hgemm_kernel(
    const __nv_bfloat16* __restrict__ Acat, const __nv_bfloat16* __restrict__ Bcat,
    const float* __restrict__ bias, const float* __restrict__ res,
    float* __restrict__ C, int M, int KC, int Nc, int mode)
{
    __shared__ __align__(1024) __nv_bfloat16 As[2][HG_BM * HG_BK];
    __shared__ __align__(1024) __nv_bfloat16 Bs[2][HG_BN * HG_BK];

    const int tid  = threadIdx.x;
    const int wid  = tid >> 5;
    const int lane = tid & 31;
    const int row0 = blockIdx.y * HG_BM;
    const int col0 = blockIdx.x * HG_BN;
    const int wm = wid & 3;
    const int wn = wid >> 2;

    float acc[2][8][4];
#pragma unroll
    for (int mt = 0; mt < 2; mt++)
#pragma unroll
        for (int nt = 0; nt < 8; nt++)
#pragma unroll
            for (int q = 0; q < 4; q++) acc[mt][nt][q] = 0.f;

    const int cp_row = tid >> 1;
    const int cp_q0  = (tid & 1) * 4;

    auto issue_chunk = [&](int kc, int buf) {
        const __nv_bfloat16* srcA =
            Acat + (size_t)(row0 + cp_row) * KC + kc * HG_BK + cp_q0 * 8;
        const __nv_bfloat16* srcB =
            Bcat + (size_t)(col0 + cp_row) * KC + kc * HG_BK + cp_q0 * 8;
        uint32_t sAb = s2u(As[buf]);
        uint32_t sBb = s2u(Bs[buf]);
#pragma unroll
        for (int q = 0; q < 4; q++) {
            uint32_t off = cp_row * 128 + (cp_q0 + q) * 16;
            off ^= (off >> 3) & 0x70;
            cpa16(sAb + off, srcA + q * 8);
            cpa16(sBb + off, srcB + q * 8);
        }
        cpa_commit();
    };

    const int r8  = lane & 7;
    const int mat = lane >> 3;
    const uint32_t a_row = wm * 32 + ((mat & 1) ? 8 : 0) + r8;
    const uint32_t a_kb  = (mat & 2) ? 16u : 0u;
    const uint32_t b_row = wn * 64 + ((mat & 2) ? 8 : 0) + r8;
    const uint32_t b_kb  = (mat & 1) ? 16u : 0u;

    issue_chunk(0, 0);

    const int NCH = KC / HG_BK;
    for (int kc = 0; kc < NCH; kc++) {
        int buf = kc & 1;
        bool more = (kc + 1 < NCH);
        if (more) issue_chunk(kc + 1, buf ^ 1);
        if (more) cpa_wait<1>(); else cpa_wait<0>();
        __syncthreads();

        const uint32_t sA = s2u(As[buf]);
        const uint32_t sB = s2u(Bs[buf]);
#pragma unroll
        for (int ks = 0; ks < 4; ks++) {
            const uint32_t kb0 = ks * 32;
            uint32_t afr[2][4], bfr[4][4];
#pragma unroll
            for (int mt = 0; mt < 2; mt++) {
                uint32_t off = (a_row + mt * 16) * 128 + kb0 + a_kb;
                off ^= (off >> 3) & 0x70;
                ldm_x4(afr[mt], sA + off);
            }
#pragma unroll
            for (int nt2 = 0; nt2 < 4; nt2++) {
                uint32_t off = (b_row + nt2 * 16) * 128 + kb0 + b_kb;
                off ^= (off >> 3) & 0x70;
                ldm_x4(bfr[nt2], sB + off);
            }
#pragma unroll
            for (int mt = 0; mt < 2; mt++)
#pragma unroll
                for (int nt = 0; nt < 8; nt++)
                    mma_bf16(acc[mt][nt], afr[mt], &bfr[nt >> 1][(nt & 1) * 2]);
        }
        __syncthreads();
    }

    // epilogue
#pragma unroll
    for (int mt = 0; mt < 2; mt++) {
        int rbase = row0 + wm * 32 + mt * 16 + (lane >> 2);
#pragma unroll
        for (int nt = 0; nt < 8; nt++) {
            int col = col0 + wn * 64 + nt * 8 + 2 * (lane & 3);
            if (col >= Nc) continue;
            float2 bv = *(const float2*)&bias[col];
#pragma unroll
            for (int h = 0; h < 2; h++) {
                int row = rbase + h * 8;
                if (row >= M) continue;
                float v0 = acc[mt][nt][2 * h + 0] + bv.x;
                float v1 = acc[mt][nt][2 * h + 1] + bv.y;
                if (mode <= 1) {
                    v0 = v0 > 0.f ? v0 : 0.f;
                    v1 = v1 > 0.f ? v1 : 0.f;
                }
                if (mode == 1) {
                    float2 rv = *(const float2*)&res[(size_t)row * Nc + col];
                    v0 += rv.x; v1 += rv.y;
                }
                *(float2*)&C[(size_t)row * Nc + col] = make_float2(v0, v1);
            }
        }
    }
}

// ---------------- launch ----------------------------------------------------
extern "C" void kernel_launch(void* const* d_in, const int* in_sizes, int n_in,
                              void* d_out, int out_size) {
    const float* x      = (const float*)d_in[0];
    const int*   src    = (const int*)  d_in[1];
    const int*   dst    = (const int*)  d_in[2];
    const float* self_w = (const float*)d_in[3];
    const float* ppi_w  = (const float*)d_in[4];
    const float* W_in   = (const float*)d_in[5];
    const float* b_in   = (const float*)d_in[6];
    const float* W1     = (const float*)d_in[7];
    const float* b1     = (const float*)d_in[8];
    const float* W2     = (const float*)d_in[9];
    const float* b2     = (const float*)d_in[10];
    const float* W_out  = (const float*)d_in[11];
    const float* b_out  = (const float*)d_in[12];
    float* out = (float*)d_out;

    const int n = in_sizes[0] / DIN;   // 50000
    const int e = in_sizes[1];         // 800000

    float *p_h, *p_h2, *p_res;
    __nv_bfloat16 *p_acat, *p_bwin, *p_bw1, *p_bw2, *p_bout;
    cudaGetSymbolAddress((void**)&p_h,    g_h);
    cudaGetSymbolAddress((void**)&p_h2,   g_h2);
    cudaGetSymbolAddress((void**)&p_res,  g_res);
    cudaGetSymbolAddress((void**)&p_acat, g_acat);
    cudaGetSymbolAddress((void**)&p_bwin, g_bwin);
    cudaGetSymbolAddress((void**)&p_bw1,  g_bw1);
    cudaGetSymbolAddress((void**)&p_bw2,  g_bw2);
    cudaGetSymbolAddress((void**)&p_bout, g_bout);

    // ---- CSR build (deterministic: segments sorted by edge id) ----
    const int nb = (n + 1023) / 1024;
    zero_cnt_kernel<<<(n + 255) / 256, 256>>>(n);
    hist_kernel<<<(e + 255) / 256, 256>>>(dst, e);
    scan1_kernel<<<nb, 1024>>>(n);
    scan2_kernel<<<1, 32>>>(nb, n);
    scan3_kernel<<<(n + 255) / 256, 256>>>(n);
    fill_kernel<<<(e + 255) / 256, 256>>>(dst, e);
    segsort_kernel<<<(n + 127) / 128, 128>>>(n);
    permute_kernel<<<(e + 255) / 256, 256>>>(src, ppi_w, self_w, e);

    // weight splits (independent, run early)
    wsplit_kernel<<<(DH * DIN + 255) / 256, 256>>>(W_in, p_bwin, DIN, DH);
    wsplit_kernel<<<(DH * DH + 255) / 256, 256>>>(W1, p_bw1, DH, DH);
    wsplit_kernel<<<(DH * DH + 255) / 256, 256>>>(W2, p_bw2, DH, DH);
    wsplit_kernel<<<(NL * DH + 255) / 256, 256>>>(W_out, p_bout, DH, NL);

    int aggBlocks = (n * 32 + 255) / 256;
    dim3 g1(1, NNPAD / HG_BM);            // (1, 391)
    dim3 gout(NLPAD / HG_BN, NNPAD / HG_BM);   // (8, 391)

    // h = relu(x @ W_in + b_in)
    xsplit_kernel<<<(NN * (DIN / 4) + 255) / 256, 256>>>(x);
    hgemm_kernel<<<g1, 256>>>(p_acat, p_bwin, b_in, nullptr, p_h, n, KC6, DH, 0);

    // layer 1: agg writes split A + res; gemm -> h2
    agg_kernel<<<aggBlocks, 256>>>(p_h, n);
    hgemm_kernel<<<g1, 256>>>(p_acat, p_bw1, b1, p_res, p_h2, n, KC3, DH, 1);

    // layer 2
    agg_kernel<<<aggBlocks, 256>>>(p_h2, n);
    hgemm_kernel<<<g1, 256>>>(p_acat, p_bw2, b2, p_res, p_h, n, KC3, DH, 1);

    // output
    hsplit_kernel<<<(NN * (DH / 4) + 255) / 256, 256>>>(p_h);
    hgemm_kernel<<<gout, 256>>>(p_acat, p_bout, b_out, nullptr, out, n, KC3, NL, 2);
}

// round 14
// speedup vs baseline: 1.0968x; 1.0968x over previous
#include <cuda_runtime.h>
#include <cuda_bf16.h>
#include <cstddef>
#include <cstdint>

#define NN    50000
#define EE    800000
#define DIN   256
#define DH    128
#define NL    1000
#define NLPAD 1024
#define NNPAD 50048          // 391 * 128
#define KCAT  384            // 3 * 128 (hi|hi|lo concat)

// ---------------- scratch (static device allocations; no cudaMalloc) -------
__device__ float g_h   [NN * DH];
__device__ float g_h2  [NN * DH];
__device__ float g_agg [NN * DH];
__device__ float g_res [NN * DH];
__device__ int   g_rowptr[NN + 1];
__device__ int   g_cursor[NN];
__device__ int   g_perm  [EE];
__device__ int   g_srcp  [EE];
__device__ float g_wp    [EE];
__device__ float g_ws    [EE];
__device__ int   g_bsum  [64];
__device__ int   g_boff  [64];
__device__ __nv_bfloat16 g_acat[(size_t)NNPAD * KCAT];   // tail rows stay 0
__device__ __nv_bfloat16 g_bcat[(size_t)NLPAD * KCAT];   // rows 1000..1023 stay 0

// ---------------- packed fp32x2 helpers (sm_103a FFMA2 path) ---------------
typedef unsigned long long f32x2_t;

__device__ __forceinline__ void fma2(f32x2_t& d, f32x2_t a, f32x2_t b) {
    asm("fma.rn.f32x2 %0, %1, %2, %3;" : "=l"(d) : "l"(a), "l"(b), "l"(d));
}
__device__ __forceinline__ void unpack2(f32x2_t v, float& lo, float& hi) {
    asm("mov.b64 {%0, %1}, %2;" : "=f"(lo), "=f"(hi) : "l"(v));
}

// ---------------- mma.sync / cp.async helpers (baseline PTX) ---------------
__device__ __forceinline__ uint32_t s2u(const void* p) {
    uint32_t a;
    asm("{ .reg .u64 t; cvta.to.shared.u64 t, %1; cvt.u32.u64 %0, t; }"
        : "=r"(a) : "l"(p));
    return a;
}
__device__ __forceinline__ void ldm_x4(uint32_t* d, uint32_t addr) {
    asm volatile("ldmatrix.sync.aligned.m8n8.x4.shared.b16 {%0,%1,%2,%3}, [%4];"
                 : "=r"(d[0]), "=r"(d[1]), "=r"(d[2]), "=r"(d[3]) : "r"(addr));
}
__device__ __forceinline__ void mma_bf16(float* c, const uint32_t* a, const uint32_t* b) {
    asm volatile(
        "mma.sync.aligned.m16n8k16.row.col.f32.bf16.bf16.f32 "
        "{%0,%1,%2,%3}, {%4,%5,%6,%7}, {%8,%9}, {%0,%1,%2,%3};"
        : "+f"(c[0]), "+f"(c[1]), "+f"(c[2]), "+f"(c[3])
        : "r"(a[0]), "r"(a[1]), "r"(a[2]), "r"(a[3]), "r"(b[0]), "r"(b[1]));
}
__device__ __forceinline__ void cpa16(uint32_t dst, const void* src) {
    asm volatile("cp.async.cg.shared.global [%0], [%1], 16;"
                 :: "r"(dst), "l"(src) : "memory");
}
__device__ __forceinline__ void cpa_commit() {
    asm volatile("cp.async.commit_group;" ::: "memory");
}
template <int N>
__device__ __forceinline__ void cpa_wait() {
    asm volatile("cp.async.wait_group %0;" :: "n"(N) : "memory");
}

// ---------------- CSR build kernels ----------------------------------------
__global__ void zero_cnt_kernel(int n) {
    int i = blockIdx.x * blockDim.x + threadIdx.x;
    if (i < n) g_cursor[i] = 0;
}

__global__ void hist_kernel(const int* __restrict__ dst, int e) {
    int i = blockIdx.x * blockDim.x + threadIdx.x;
    if (i < e) atomicAdd(&g_cursor[dst[i]], 1);
}

__global__ void scan1_kernel(int n) {
    __shared__ int sdata[1024];
    int tid = threadIdx.x;
    int i = blockIdx.x * 1024 + tid;
    int v = (i < n) ? g_cursor[i] : 0;
    sdata[tid] = v;
    __syncthreads();
    for (int off = 1; off < 1024; off <<= 1) {
        int t = (tid >= off) ? sdata[tid - off] : 0;
        __syncthreads();
        sdata[tid] += t;
        __syncthreads();
    }
    if (i < n) g_rowptr[i] = sdata[tid] - v;
    if (tid == 1023) g_bsum[blockIdx.x] = sdata[1023];
}

// warp-shuffle scan of <=64 block sums (replaces 1-thread serial loop whose
// 49 dependent L2 round-trips cost ~6.5us)
__global__ void scan2_kernel(int nb, int n) {
    int lane = threadIdx.x;
    int v0 = (lane < nb) ? g_bsum[lane] : 0;
    int v1 = (lane + 32 < nb) ? g_bsum[lane + 32] : 0;
    int s0 = v0;
#pragma unroll
    for (int o = 1; o < 32; o <<= 1) {
        int t = __shfl_up_sync(0xFFFFFFFFu, s0, o);
        if (lane >= o) s0 += t;
    }
    int tot0 = __shfl_sync(0xFFFFFFFFu, s0, 31);
    int s1 = v1;
#pragma unroll
    for (int o = 1; o < 32; o <<= 1) {
        int t = __shfl_up_sync(0xFFFFFFFFu, s1, o);
        if (lane >= o) s1 += t;
    }
    int tot1 = __shfl_sync(0xFFFFFFFFu, s1, 31);
    if (lane < nb) g_boff[lane] = s0 - v0;
    if (lane + 32 < nb) g_boff[lane + 32] = tot0 + s1 - v1;
    if (lane == 0) g_rowptr[n] = tot0 + tot1;
}

__global__ void scan3_kernel(int n) {
    int i = blockIdx.x * blockDim.x + threadIdx.x;
    if (i < n) {
        int v = g_rowptr[i] + g_boff[i >> 10];
        g_rowptr[i] = v;
        g_cursor[i] = v;
    }
}

__global__ void fill_kernel(const int* __restrict__ dst, int e) {
    int i = blockIdx.x * blockDim.x + threadIdx.x;
    if (i < e) {
        int d = dst[i];
        int p = atomicAdd(&g_cursor[d], 1);
        g_perm[p] = i;
    }
}

__global__ void segsort_kernel(int n) {
    int node = blockIdx.x * blockDim.x + threadIdx.x;
    if (node >= n) return;
    int b = g_rowptr[node], e = g_rowptr[node + 1];
    for (int i = b + 1; i < e; i++) {
        int key = g_perm[i];
        int j = i - 1;
        while (j >= b && g_perm[j] > key) { g_perm[j + 1] = g_perm[j]; j--; }
        g_perm[j + 1] = key;
    }
}

__global__ void permute_kernel(const int* __restrict__ src,
                               const float* __restrict__ ppi_w,
                               const float* __restrict__ self_w, int e) {
    int j = blockIdx.x * blockDim.x + threadIdx.x;
    if (j < e) {
        int ed = g_perm[j];
        g_srcp[j] = src[ed];
        g_wp[j]   = ppi_w[ed];
        g_ws[j]   = self_w[ed];
    }
}

// ---------------- fused aggregation ----------------------------------------
__global__ void agg_kernel(const float* __restrict__ h, int n) {
    int warp = (blockIdx.x * blockDim.x + threadIdx.x) >> 5;
    int lane = threadIdx.x & 31;
    if (warp >= n) return;
    int beg = g_rowptr[warp], end = g_rowptr[warp + 1];
    float4 ap = make_float4(0.f, 0.f, 0.f, 0.f);
    float4 as = make_float4(0.f, 0.f, 0.f, 0.f);
    for (int j = beg; j < end; j++) {
        int   s  = g_srcp[j];
        float wp = g_wp[j];
        float ws = g_ws[j];
        const float4 v = *(const float4*)&h[(size_t)s * DH + lane * 4];
        ap.x += wp * v.x; ap.y += wp * v.y; ap.z += wp * v.z; ap.w += wp * v.w;
        as.x += ws * v.x; as.y += ws * v.y; as.z += ws * v.z; as.w += ws * v.w;
    }
    *(float4*)&g_agg[(size_t)warp * DH + lane * 4] = ap;
    *(float4*)&g_res[(size_t)warp * DH + lane * 4] = as;
}

// ---------------- SGEMM (fp32x2): used for the 3 small GEMMs ---------------
#define BM 128
#define BN 128
#define BK 8
#define TM 8
#define TN 8

__global__ void __launch_bounds__(256, 2) sgemm_kernel(
    const float* __restrict__ A, const float* __restrict__ B,
    const float* __restrict__ bias, const float* __restrict__ res,
    float* __restrict__ C, int M, int Nc, int K, int epi)
{
    __shared__ float As [2][BK][BM];
    __shared__ float Bs2[2][BK][2 * BN];

    const int row0 = blockIdx.y * BM;
    const int col0 = blockIdx.x * BN;
    const int tid  = threadIdx.x;
    const int tx = tid % 16;
    const int ty = tid / 16;
    const int a_row = tid / 2;
    const int a_col = (tid % 2) * 4;
    const int b_row = tid / 32;
    const int b_col = (tid % 32) * 4;

    f32x2_t acc2[TM / 2][TN];
#pragma unroll
    for (int i = 0; i < TM / 2; i++)
#pragma unroll
        for (int j = 0; j < TN; j++) acc2[i][j] = 0ull;

    auto ldgA = [&](int kt) -> float4 {
        float4 v = make_float4(0.f, 0.f, 0.f, 0.f);
        int gr = row0 + a_row;
        if (gr < M) v = *(const float4*)&A[(size_t)gr * K + kt + a_col];
        return v;
    };
    auto ldgB = [&](int kt) -> float4 {
        int gbr = kt + b_row;
        int gbc = col0 + b_col;
        float4 v = make_float4(0.f, 0.f, 0.f, 0.f);
        if (gbc + 3 < Nc) {
            v = *(const float4*)&B[(size_t)gbr * Nc + gbc];
        }
        return v;
    };
    auto stsA = [&](int buf, float4 v) {
        As[buf][a_col + 0][a_row] = v.x;
        As[buf][a_col + 1][a_row] = v.y;
        As[buf][a_col + 2][a_row] = v.z;
        As[buf][a_col + 3][a_row] = v.w;
    };
    auto stsB = [&](int buf, float4 v) {
        *(float4*)&Bs2[buf][b_row][b_col * 2]     = make_float4(v.x, v.x, v.y, v.y);
        *(float4*)&Bs2[buf][b_row][b_col * 2 + 4] = make_float4(v.z, v.z, v.w, v.w);
    };

    const int nk = K / BK;
    {
        float4 av = ldgA(0);
        float4 bv = ldgB(0);
        stsA(0, av);
        stsB(0, bv);
        __syncthreads();
    }

    for (int t = 0; t < nk; t++) {
        int cur = t & 1, nxt = cur ^ 1;
        float4 av, bv;
        bool more = (t + 1 < nk);
        if (more) { av = ldgA((t + 1) * BK); bv = ldgB((t + 1) * BK); }
#pragma unroll
        for (int kk = 0; kk < BK; kk++) {
            f32x2_t a2[TM / 2];
#pragma unroll
            for (int rp = 0; rp < TM / 2; rp++)
                a2[rp] = *(const f32x2_t*)&As[cur][kk][ty * TM + 2 * rp];
            f32x2_t bd[TN];
#pragma unroll
            for (int j = 0; j < TN; j++)
                bd[j] = *(const f32x2_t*)&Bs2[cur][kk][(tx + 16 * j) * 2];
#pragma unroll
            for (int rp = 0; rp < TM / 2; rp++)
#pragma unroll
                for (int j = 0; j < TN; j++)
                    fma2(acc2[rp][j], a2[rp], bd[j]);
        }
        if (more) {
            stsA(nxt, av);
            stsB(nxt, bv);
            __syncthreads();
        }
    }

#pragma unroll
    for (int rp = 0; rp < TM / 2; rp++) {
#pragma unroll
        for (int j = 0; j < TN; j++) {
            float vlo, vhi;
            unpack2(acc2[rp][j], vlo, vhi);
            int col = col0 + tx + 16 * j;
            if (col >= Nc) continue;
            float vv[2] = {vlo, vhi};
#pragma unroll
            for (int q = 0; q < 2; q++) {
                int row = row0 + ty * TM + 2 * rp + q;
                if (row >= M) continue;
                float v = vv[q] + bias[col];
                if (epi <= 1) v = v > 0.f ? v : 0.f;
                if (epi == 1) v += res[(size_t)row * Nc + col];
                C[(size_t)row * Nc + col] = v;
            }
        }
    }
}

// ---------------- bf16 split-prep kernels -----------------------------------
// A_cat[m] = [hi(h[m])|hi(h[m])|lo(h[m])]
__global__ void hsplit_kernel(const float* __restrict__ h) {
    int idx = blockIdx.x * blockDim.x + threadIdx.x;
    if (idx >= NN * DH) return;
    int m = idx / DH, k = idx % DH;
    float v = h[idx];
    __nv_bfloat16 hi = __float2bfloat16(v);
    __nv_bfloat16 lo = __float2bfloat16(v - __bfloat162float(hi));
    size_t base = (size_t)m * KCAT;
    g_acat[base + k]       = hi;
    g_acat[base + 128 + k] = hi;
    g_acat[base + 256 + k] = lo;
}

// B_cat[n] = [hi(W[.][n])|lo(W[.][n])|hi(W[.][n])]  (W_out is [128][1000])
__global__ void wsplit_kernel(const float* __restrict__ W) {
    int idx = blockIdx.x * blockDim.x + threadIdx.x;
    if (idx >= NL * DH) return;
    int n = idx / DH, k = idx % DH;
    float v = W[(size_t)k * NL + n];
    __nv_bfloat16 hi = __float2bfloat16(v);
    __nv_bfloat16 lo = __float2bfloat16(v - __bfloat162float(hi));
    size_t base = (size_t)n * KCAT;
    g_bcat[base + k]       = hi;
    g_bcat[base + 128 + k] = lo;
    g_bcat[base + 256 + k] = hi;
}

// ---------------- HMMA out-GEMM: C[M,1000] = Acat @ Bcat^T + bias ----------
// CTA 128x256, 512 threads (16 warps: 4 M x 4 N), warp tile 32x64.
// cp.async double-buffered; dynamic smem 96KB (A 2x16KB + B 2x32KB).
#define HG_BM 128
#define HG_BN 256
#define HG_BK 64
#define OG_SMEM (HG_BM * HG_BK * 2 * 2 + HG_BN * HG_BK * 2 * 2 + 1024)

__global__ void __launch_bounds__(512, 1) outgemm_kernel(
    const float* __restrict__ bias, float* __restrict__ C, int M)
{
    extern __shared__ char dyn[];
    const uint32_t ab = (s2u(dyn) + 1023u) & ~1023u;
    const uint32_t sAb[2] = {ab, ab + 16384u};
    const uint32_t sBb[2] = {ab + 32768u, ab + 32768u + 32768u};

    const int tid  = threadIdx.x;
    const int wid  = tid >> 5;
    const int lane = tid & 31;
    const int row0 = blockIdx.y * HG_BM;
    const int col0 = blockIdx.x * HG_BN;
    const int wm = wid & 3;           // 0..3 -> 32-row slab
    const int wn = wid >> 2;          // 0..3 -> 64-col slab

    float acc[2][8][4];
#pragma unroll
    for (int mt = 0; mt < 2; mt++)
#pragma unroll
        for (int nt = 0; nt < 8; nt++)
#pragma unroll
            for (int q = 0; q < 4; q++) acc[mt][nt][q] = 0.f;

    auto issue_chunk = [&](int kc, int buf) {
        // (128 + 256) rows * 8 16B-units = 3072 units / 512 threads = 6 each
#pragma unroll
        for (int k = 0; k < 6; k++) {
            int u = tid + k * 512;
            if (u < HG_BM * 8) {
                int row = u >> 3, q = u & 7;
                uint32_t off = row * 128 + q * 16;
                off ^= (off >> 3) & 0x70;
                cpa16(sAb[buf] + off,
                      g_acat + (size_t)(row0 + row) * KCAT + kc * HG_BK + q * 8);
            } else {
                int u2 = u - HG_BM * 8;
                int row = u2 >> 3, q = u2 & 7;
                uint32_t off = row * 128 + q * 16;
                off ^= (off >> 3) & 0x70;
                cpa16(sBb[buf] + off,
                      g_bcat + (size_t)(col0 + row) * KCAT + kc * HG_BK + q * 8);
            }
        }
        cpa_commit();
    };

    // ldmatrix lane addressing (fragment mapping verified R11/R12):
    const int r8  = lane & 7;
    const int mat = lane >> 3;
    const uint32_t a_row = wm * 32 + ((mat & 1) ? 8 : 0) + r8;   // + mt*16
    const uint32_t a_kb  = (mat & 2) ? 16u : 0u;
    const uint32_t b_row = wn * 64 + ((mat & 2) ? 8 : 0) + r8;   // + nt2*16
    const uint32_t b_kb  = (mat & 1) ? 16u : 0u;

    issue_chunk(0, 0);

    const int NCH = KCAT / HG_BK;   // 6
    for (int kc = 0; kc < NCH; kc++) {
        int buf = kc & 1;
        bool more = (kc + 1 < NCH);
        if (more) issue_chunk(kc + 1, buf ^ 1);
        if (more) cpa_wait<1>(); else cpa_wait<0>();
        __syncthreads();

        const uint32_t sA = sAb[buf];
        const uint32_t sB = sBb[buf];
#pragma unroll
        for (int ks = 0; ks < 4; ks++) {
            const uint32_t kb0 = ks * 32;
            uint32_t afr[2][4], bfr[4][4];
#pragma unroll
            for (int mt = 0; mt < 2; mt++) {
                uint32_t off = (a_row + mt * 16) * 128 + kb0 + a_kb;
                off ^= (off >> 3) & 0x70;
                ldm_x4(afr[mt], sA + off);
            }
#pragma unroll
            for (int nt2 = 0; nt2 < 4; nt2++) {
                uint32_t off = (b_row + nt2 * 16) * 128 + kb0 + b_kb;
                off ^= (off >> 3) & 0x70;
                ldm_x4(bfr[nt2], sB + off);
            }
#pragma unroll
            for (int mt = 0; mt < 2; mt++)
#pragma unroll
                for (int nt = 0; nt < 8; nt++)
                    mma_bf16(acc[mt][nt], afr[mt], &bfr[nt >> 1][(nt & 1) * 2]);
        }
        __syncthreads();
    }

    // epilogue
#pragma unroll
    for (int mt = 0; mt < 2; mt++) {
        int rbase = row0 + wm * 32 + mt * 16 + (lane >> 2);
#pragma unroll
        for (int nt = 0; nt < 8; nt++) {
            int col = col0 + wn * 64 + nt * 8 + 2 * (lane & 3);
            if (col >= NL) continue;
            float2 bv = *(const float2*)&bias[col];
            if (rbase < M) {
                float2 o = make_float2(acc[mt][nt][0] + bv.x, acc[mt][nt][1] + bv.y);
                *(float2*)&C[(size_t)rbase * NL + col] = o;
            }
            if (rbase + 8 < M) {
                float2 o = make_float2(acc[mt][nt][2] + bv.x, acc[mt][nt][3] + bv.y);
                *(float2*)&C[(size_t)(rbase + 8) * NL + col] = o;
            }
        }
    }
}

// ---------------- launch ----------------------------------------------------
extern "C" void kernel_launch(void* const* d_in, const int* in_sizes, int n_in,
                              void* d_out, int out_size) {
    const float* x      = (const float*)d_in[0];
    const int*   src    = (const int*)  d_in[1];
    const int*   dst    = (const int*)  d_in[2];
    const float* self_w = (const float*)d_in[3];
    const float* ppi_w  = (const float*)d_in[4];
    const float* W_in   = (const float*)d_in[5];
    const float* b_in   = (const float*)d_in[6];
    const float* W1     = (const float*)d_in[7];
    const float* b1     = (const float*)d_in[8];
    const float* W2     = (const float*)d_in[9];
    const float* b2     = (const float*)d_in[10];
    const float* W_out  = (const float*)d_in[11];
    const float* b_out  = (const float*)d_in[12];
    float* out = (float*)d_out;

    const int n = in_sizes[0] / DIN;   // 50000
    const int e = in_sizes[1];         // 800000

    float *p_h, *p_h2, *p_agg, *p_res;
    cudaGetSymbolAddress((void**)&p_h,   g_h);
    cudaGetSymbolAddress((void**)&p_h2,  g_h2);
    cudaGetSymbolAddress((void**)&p_agg, g_agg);
    cudaGetSymbolAddress((void**)&p_res, g_res);

    cudaFuncSetAttribute(outgemm_kernel,
                         cudaFuncAttributeMaxDynamicSharedMemorySize, OG_SMEM);

    // ---- CSR build (deterministic: segments sorted by edge id) ----
    const int nb = (n + 1023) / 1024;
    zero_cnt_kernel<<<(n + 255) / 256, 256>>>(n);
    hist_kernel<<<(e + 255) / 256, 256>>>(dst, e);
    scan1_kernel<<<nb, 1024>>>(n);
    scan2_kernel<<<1, 32>>>(nb, n);
    scan3_kernel<<<(n + 255) / 256, 256>>>(n);
    fill_kernel<<<(e + 255) / 256, 256>>>(dst, e);
    segsort_kernel<<<(n + 127) / 128, 128>>>(n);
    permute_kernel<<<(e + 255) / 256, 256>>>(src, ppi_w, self_w, e);

    dim3 gin((DH + BN - 1) / BN, (n + BM - 1) / BM);     // (1, 391)
    int aggBlocks = (n * 32 + 255) / 256;

    // weight split can run early (independent)
    wsplit_kernel<<<(NL * DH + 255) / 256, 256>>>(W_out);

    // h = relu(x @ W_in + b_in)
    sgemm_kernel<<<gin, 256>>>(x, W_in, b_in, nullptr, p_h, n, DH, DIN, 0);

    // layer 1
    agg_kernel<<<aggBlocks, 256>>>(p_h, n);
    sgemm_kernel<<<gin, 256>>>(p_agg, W1, b1, p_res, p_h2, n, DH, DH, 1);

    // layer 2
    agg_kernel<<<aggBlocks, 256>>>(p_h2, n);
    sgemm_kernel<<<gin, 256>>>(p_agg, W2, b2, p_res, p_h, n, DH, DH, 1);

    // output: bf16 split + pipelined HMMA GEMM (BN=256)
    hsplit_kernel<<<(NN * DH + 255) / 256, 256>>>(p_h);
    dim3 gog(NLPAD / HG_BN, NNPAD / HG_BM);              // (4, 391)
    outgemm_kernel<<<gog, 512, OG_SMEM>>>(b_out, out, n);
}

// round 15
// speedup vs baseline: 1.1942x; 1.0887x over previous
#include <cuda_runtime.h>
#include <cuda_bf16.h>
#include <cstddef>
#include <cstdint>

#define NN    50000
#define EE    800000
#define DIN   256
#define DH    128
#define NL    1000
#define NLPAD 1024
#define NNPAD 50048          // 391 * 128
#define KCAT  384            // 3 * 128 (hi|hi|lo concat)

// ---------------- scratch (static device allocations; no cudaMalloc) -------
__device__ float g_h   [NN * DH];
__device__ float g_h2  [NN * DH];
__device__ float g_agg [NN * DH];
__device__ float g_res [NN * DH];
__device__ int   g_rowptr[NN + 1];
__device__ int   g_cursor[NN];
__device__ int   g_perm  [EE];
__device__ int   g_srcp  [EE];
__device__ float g_wp    [EE];
__device__ float g_ws    [EE];
__device__ int   g_bsum  [64];
__device__ int   g_boff  [64];
__device__ __nv_bfloat16 g_acat[(size_t)NNPAD * KCAT];   // tail rows stay 0
__device__ __nv_bfloat16 g_bcat[(size_t)NLPAD * KCAT];   // rows 1000..1023 stay 0

// ---------------- packed fp32x2 helpers (sm_103a FFMA2 path) ---------------
typedef unsigned long long f32x2_t;

__device__ __forceinline__ void fma2(f32x2_t& d, f32x2_t a, f32x2_t b) {
    asm("fma.rn.f32x2 %0, %1, %2, %3;" : "=l"(d) : "l"(a), "l"(b), "l"(d));
}
__device__ __forceinline__ void unpack2(f32x2_t v, float& lo, float& hi) {
    asm("mov.b64 {%0, %1}, %2;" : "=f"(lo), "=f"(hi) : "l"(v));
}

// ---------------- mma.sync / cp.async helpers (baseline PTX) ---------------
__device__ __forceinline__ uint32_t s2u(const void* p) {
    uint32_t a;
    asm("{ .reg .u64 t; cvta.to.shared.u64 t, %1; cvt.u32.u64 %0, t; }"
        : "=r"(a) : "l"(p));
    return a;
}
__device__ __forceinline__ void ldm_x4(uint32_t* d, uint32_t addr) {
    asm volatile("ldmatrix.sync.aligned.m8n8.x4.shared.b16 {%0,%1,%2,%3}, [%4];"
                 : "=r"(d[0]), "=r"(d[1]), "=r"(d[2]), "=r"(d[3]) : "r"(addr));
}
__device__ __forceinline__ void mma_bf16(float* c, const uint32_t* a, const uint32_t* b) {
    asm volatile(
        "mma.sync.aligned.m16n8k16.row.col.f32.bf16.bf16.f32 "
        "{%0,%1,%2,%3}, {%4,%5,%6,%7}, {%8,%9}, {%0,%1,%2,%3};"
        : "+f"(c[0]), "+f"(c[1]), "+f"(c[2]), "+f"(c[3])
        : "r"(a[0]), "r"(a[1]), "r"(a[2]), "r"(a[3]), "r"(b[0]), "r"(b[1]));
}
__device__ __forceinline__ void cpa16(uint32_t dst, const void* src) {
    asm volatile("cp.async.cg.shared.global [%0], [%1], 16;"
                 :: "r"(dst), "l"(src) : "memory");
}
__device__ __forceinline__ void cpa_commit() {
    asm volatile("cp.async.commit_group;" ::: "memory");
}
template <int N>
__device__ __forceinline__ void cpa_wait() {
    asm volatile("cp.async.wait_group %0;" :: "n"(N) : "memory");
}

// ---------------- CSR build kernels ----------------------------------------
__global__ void zero_cnt_kernel(int n) {
    int i = blockIdx.x * blockDim.x + threadIdx.x;
    if (i < n) g_cursor[i] = 0;
}

__global__ void hist_kernel(const int* __restrict__ dst, int e) {
    int i = blockIdx.x * blockDim.x + threadIdx.x;
    if (i < e) atomicAdd(&g_cursor[dst[i]], 1);
}

__global__ void scan1_kernel(int n) {
    __shared__ int sdata[1024];
    int tid = threadIdx.x;
    int i = blockIdx.x * 1024 + tid;
    int v = (i < n) ? g_cursor[i] : 0;
    sdata[tid] = v;
    __syncthreads();
    for (int off = 1; off < 1024; off <<= 1) {
        int t = (tid >= off) ? sdata[tid - off] : 0;
        __syncthreads();
        sdata[tid] += t;
        __syncthreads();
    }
    if (i < n) g_rowptr[i] = sdata[tid] - v;
    if (tid == 1023) g_bsum[blockIdx.x] = sdata[1023];
}

// warp-shuffle scan of <=64 block sums
__global__ void scan2_kernel(int nb, int n) {
    int lane = threadIdx.x;
    int v0 = (lane < nb) ? g_bsum[lane] : 0;
    int v1 = (lane + 32 < nb) ? g_bsum[lane + 32] : 0;
    int s0 = v0;
#pragma unroll
    for (int o = 1; o < 32; o <<= 1) {
        int t = __shfl_up_sync(0xFFFFFFFFu, s0, o);
        if (lane >= o) s0 += t;
    }
    int tot0 = __shfl_sync(0xFFFFFFFFu, s0, 31);
    int s1 = v1;
#pragma unroll
    for (int o = 1; o < 32; o <<= 1) {
        int t = __shfl_up_sync(0xFFFFFFFFu, s1, o);
        if (lane >= o) s1 += t;
    }
    int tot1 = __shfl_sync(0xFFFFFFFFu, s1, 31);
    if (lane < nb) g_boff[lane] = s0 - v0;
    if (lane + 32 < nb) g_boff[lane + 32] = tot0 + s1 - v1;
    if (lane == 0) g_rowptr[n] = tot0 + tot1;
}

__global__ void scan3_kernel(int n) {
    int i = blockIdx.x * blockDim.x + threadIdx.x;
    if (i < n) {
        int v = g_rowptr[i] + g_boff[i >> 10];
        g_rowptr[i] = v;
        g_cursor[i] = v;
    }
}

__global__ void fill_kernel(const int* __restrict__ dst, int e) {
    int i = blockIdx.x * blockDim.x + threadIdx.x;
    if (i < e) {
        int d = dst[i];
        int p = atomicAdd(&g_cursor[d], 1);
        g_perm[p] = i;
    }
}

__global__ void segsort_kernel(int n) {
    int node = blockIdx.x * blockDim.x + threadIdx.x;
    if (node >= n) return;
    int b = g_rowptr[node], e = g_rowptr[node + 1];
    for (int i = b + 1; i < e; i++) {
        int key = g_perm[i];
        int j = i - 1;
        while (j >= b && g_perm[j] > key) { g_perm[j + 1] = g_perm[j]; j--; }
        g_perm[j + 1] = key;
    }
}

__global__ void permute_kernel(const int* __restrict__ src,
                               const float* __restrict__ ppi_w,
                               const float* __restrict__ self_w, int e) {
    int j = blockIdx.x * blockDim.x + threadIdx.x;
    if (j < e) {
        int ed = g_perm[j];
        g_srcp[j] = src[ed];
        g_wp[j]   = ppi_w[ed];
        g_ws[j]   = self_w[ed];
    }
}

// ---------------- fused aggregation ----------------------------------------
__global__ void agg_kernel(const float* __restrict__ h, int n) {
    int warp = (blockIdx.x * blockDim.x + threadIdx.x) >> 5;
    int lane = threadIdx.x & 31;
    if (warp >= n) return;
    int beg = g_rowptr[warp], end = g_rowptr[warp + 1];
    float4 ap = make_float4(0.f, 0.f, 0.f, 0.f);
    float4 as = make_float4(0.f, 0.f, 0.f, 0.f);
    for (int j = beg; j < end; j++) {
        int   s  = g_srcp[j];
        float wp = g_wp[j];
        float ws = g_ws[j];
        const float4 v = *(const float4*)&h[(size_t)s * DH + lane * 4];
        ap.x += wp * v.x; ap.y += wp * v.y; ap.z += wp * v.z; ap.w += wp * v.w;
        as.x += ws * v.x; as.y += ws * v.y; as.z += ws * v.z; as.w += ws * v.w;
    }
    *(float4*)&g_agg[(size_t)warp * DH + lane * 4] = ap;
    *(float4*)&g_res[(size_t)warp * DH + lane * 4] = as;
}

// ---------------- SGEMM (fp32x2): used for the 3 small GEMMs ---------------
// epi 0: relu   epi 1: relu+res   epi 3: relu+res AND write [hi|hi|lo] split
#define BM 128
#define BN 128
#define BK 8
#define TM 8
#define TN 8

__global__ void __launch_bounds__(256, 2) sgemm_kernel(
    const float* __restrict__ A, const float* __restrict__ B,
    const float* __restrict__ bias, const float* __restrict__ res,
    float* __restrict__ C, int M, int Nc, int K, int epi)
{
    __shared__ float As [2][BK][BM];
    __shared__ float Bs2[2][BK][2 * BN];

    const int row0 = blockIdx.y * BM;
    const int col0 = blockIdx.x * BN;
    const int tid  = threadIdx.x;
    const int tx = tid % 16;
    const int ty = tid / 16;
    const int a_row = tid / 2;
    const int a_col = (tid % 2) * 4;
    const int b_row = tid / 32;
    const int b_col = (tid % 32) * 4;

    f32x2_t acc2[TM / 2][TN];
#pragma unroll
    for (int i = 0; i < TM / 2; i++)
#pragma unroll
        for (int j = 0; j < TN; j++) acc2[i][j] = 0ull;

    auto ldgA = [&](int kt) -> float4 {
        float4 v = make_float4(0.f, 0.f, 0.f, 0.f);
        int gr = row0 + a_row;
        if (gr < M) v = *(const float4*)&A[(size_t)gr * K + kt + a_col];
        return v;
    };
    auto ldgB = [&](int kt) -> float4 {
        int gbr = kt + b_row;
        int gbc = col0 + b_col;
        float4 v = make_float4(0.f, 0.f, 0.f, 0.f);
        if (gbc + 3 < Nc) {
            v = *(const float4*)&B[(size_t)gbr * Nc + gbc];
        }
        return v;
    };
    auto stsA = [&](int buf, float4 v) {
        As[buf][a_col + 0][a_row] = v.x;
        As[buf][a_col + 1][a_row] = v.y;
        As[buf][a_col + 2][a_row] = v.z;
        As[buf][a_col + 3][a_row] = v.w;
    };
    auto stsB = [&](int buf, float4 v) {
        *(float4*)&Bs2[buf][b_row][b_col * 2]     = make_float4(v.x, v.x, v.y, v.y);
        *(float4*)&Bs2[buf][b_row][b_col * 2 + 4] = make_float4(v.z, v.z, v.w, v.w);
    };

    const int nk = K / BK;
    {
        float4 av = ldgA(0);
        float4 bv = ldgB(0);
        stsA(0, av);
        stsB(0, bv);
        __syncthreads();
    }

    for (int t = 0; t < nk; t++) {
        int cur = t & 1, nxt = cur ^ 1;
        float4 av, bv;
        bool more = (t + 1 < nk);
        if (more) { av = ldgA((t + 1) * BK); bv = ldgB((t + 1) * BK); }
#pragma unroll
        for (int kk = 0; kk < BK; kk++) {
            f32x2_t a2[TM / 2];
#pragma unroll
            for (int rp = 0; rp < TM / 2; rp++)
                a2[rp] = *(const f32x2_t*)&As[cur][kk][ty * TM + 2 * rp];
            f32x2_t bd[TN];
#pragma unroll
            for (int j = 0; j < TN; j++)
                bd[j] = *(const f32x2_t*)&Bs2[cur][kk][(tx + 16 * j) * 2];
#pragma unroll
            for (int rp = 0; rp < TM / 2; rp++)
#pragma unroll
                for (int j = 0; j < TN; j++)
                    fma2(acc2[rp][j], a2[rp], bd[j]);
        }
        if (more) {
            stsA(nxt, av);
            stsB(nxt, bv);
            __syncthreads();
        }
    }

#pragma unroll
    for (int rp = 0; rp < TM / 2; rp++) {
#pragma unroll
        for (int j = 0; j < TN; j++) {
            float vlo, vhi;
            unpack2(acc2[rp][j], vlo, vhi);
            int col = col0 + tx + 16 * j;
            if (col >= Nc) continue;
            float vv[2] = {vlo, vhi};
#pragma unroll
            for (int q = 0; q < 2; q++) {
                int row = row0 + ty * TM + 2 * rp + q;
                if (row >= M) continue;
                float v = vv[q] + bias[col];
                v = v > 0.f ? v : 0.f;          // all epi modes here use relu
                if (epi >= 1) v += res[(size_t)row * Nc + col];
                C[(size_t)row * Nc + col] = v;
                if (epi == 3) {                  // fused hsplit for out-GEMM A
                    __nv_bfloat16 hi = __float2bfloat16(v);
                    __nv_bfloat16 lo = __float2bfloat16(v - __bfloat162float(hi));
                    size_t ab = (size_t)row * KCAT + col;
                    g_acat[ab]       = hi;
                    g_acat[ab + 128] = hi;
                    g_acat[ab + 256] = lo;
                }
            }
        }
    }
}

// B_cat[n] = [hi(W[.][n])|lo(W[.][n])|hi(W[.][n])]  (W_out is [128][1000])
__global__ void wsplit_kernel(const float* __restrict__ W) {
    int idx = blockIdx.x * blockDim.x + threadIdx.x;
    if (idx >= NL * DH) return;
    int n = idx / DH, k = idx % DH;
    float v = W[(size_t)k * NL + n];
    __nv_bfloat16 hi = __float2bfloat16(v);
    __nv_bfloat16 lo = __float2bfloat16(v - __bfloat162float(hi));
    size_t base = (size_t)n * KCAT;
    g_bcat[base + k]       = hi;
    g_bcat[base + 128 + k] = lo;
    g_bcat[base + 256 + k] = hi;
}

// ---------------- HMMA out-GEMM: C[M,1000] = Acat @ Bcat^T + bias ----------
// CTA 128x256, 512 threads (16 warps: 4 M x 4 N), warp tile 32x64.
#define HG_BM 128
#define HG_BN 256
#define HG_BK 64
#define OG_SMEM (HG_BM * HG_BK * 2 * 2 + HG_BN * HG_BK * 2 * 2 + 1024)

__global__ void __launch_bounds__(512, 1) outgemm_kernel(
    const float* __restrict__ bias, float* __restrict__ C, int M)
{
    extern __shared__ char dyn[];
    const uint32_t ab = (s2u(dyn) + 1023u) & ~1023u;
    const uint32_t sAb[2] = {ab, ab + 16384u};
    const uint32_t sBb[2] = {ab + 32768u, ab + 32768u + 32768u};

    const int tid  = threadIdx.x;
    const int wid  = tid >> 5;
    const int lane = tid & 31;
    const int row0 = blockIdx.y * HG_BM;
    const int col0 = blockIdx.x * HG_BN;
    const int wm = wid & 3;
    const int wn = wid >> 2;

    float acc[2][8][4];
#pragma unroll
    for (int mt = 0; mt < 2; mt++)
#pragma unroll
        for (int nt = 0; nt < 8; nt++)
#pragma unroll
            for (int q = 0; q < 4; q++) acc[mt][nt][q] = 0.f;

    auto issue_chunk = [&](int kc, int buf) {
#pragma unroll
        for (int k = 0; k < 6; k++) {
            int u = tid + k * 512;
            if (u < HG_BM * 8) {
                int row = u >> 3, q = u & 7;
                uint32_t off = row * 128 + q * 16;
                off ^= (off >> 3) & 0x70;
                cpa16(sAb[buf] + off,
                      g_acat + (size_t)(row0 + row) * KCAT + kc * HG_BK + q * 8);
            } else {
                int u2 = u - HG_BM * 8;
                int row = u2 >> 3, q = u2 & 7;
                uint32_t off = row * 128 + q * 16;
                off ^= (off >> 3) & 0x70;
                cpa16(sBb[buf] + off,
                      g_bcat + (size_t)(col0 + row) * KCAT + kc * HG_BK + q * 8);
            }
        }
        cpa_commit();
    };

    const int r8  = lane & 7;
    const int mat = lane >> 3;
    const uint32_t a_row = wm * 32 + ((mat & 1) ? 8 : 0) + r8;
    const uint32_t a_kb  = (mat & 2) ? 16u : 0u;
    const uint32_t b_row = wn * 64 + ((mat & 2) ? 8 : 0) + r8;
    const uint32_t b_kb  = (mat & 1) ? 16u : 0u;

    issue_chunk(0, 0);

    const int NCH = KCAT / HG_BK;   // 6
    for (int kc = 0; kc < NCH; kc++) {
        int buf = kc & 1;
        bool more = (kc + 1 < NCH);
        if (more) issue_chunk(kc + 1, buf ^ 1);
        if (more) cpa_wait<1>(); else cpa_wait<0>();
        __syncthreads();

        const uint32_t sA = sAb[buf];
        const uint32_t sB = sBb[buf];
#pragma unroll
        for (int ks = 0; ks < 4; ks++) {
            const uint32_t kb0 = ks * 32;
            uint32_t afr[2][4], bfr[4][4];
#pragma unroll
            for (int mt = 0; mt < 2; mt++) {
                uint32_t off = (a_row + mt * 16) * 128 + kb0 + a_kb;
                off ^= (off >> 3) & 0x70;
                ldm_x4(afr[mt], sA + off);
            }
#pragma unroll
            for (int nt2 = 0; nt2 < 4; nt2++) {
                uint32_t off = (b_row + nt2 * 16) * 128 + kb0 + b_kb;
                off ^= (off >> 3) & 0x70;
                ldm_x4(bfr[nt2], sB + off);
            }
#pragma unroll
            for (int mt = 0; mt < 2; mt++)
#pragma unroll
                for (int nt = 0; nt < 8; nt++)
                    mma_bf16(acc[mt][nt], afr[mt], &bfr[nt >> 1][(nt & 1) * 2]);
        }
        __syncthreads();
    }

#pragma unroll
    for (int mt = 0; mt < 2; mt++) {
        int rbase = row0 + wm * 32 + mt * 16 + (lane >> 2);
#pragma unroll
        for (int nt = 0; nt < 8; nt++) {
            int col = col0 + wn * 64 + nt * 8 + 2 * (lane & 3);
            if (col >= NL) continue;
            float2 bv = *(const float2*)&bias[col];
            if (rbase < M) {
                float2 o = make_float2(acc[mt][nt][0] + bv.x, acc[mt][nt][1] + bv.y);
                *(float2*)&C[(size_t)rbase * NL + col] = o;
            }
            if (rbase + 8 < M) {
                float2 o = make_float2(acc[mt][nt][2] + bv.x, acc[mt][nt][3] + bv.y);
                *(float2*)&C[(size_t)(rbase + 8) * NL + col] = o;
            }
        }
    }
}

// ---------------- launch ----------------------------------------------------
extern "C" void kernel_launch(void* const* d_in, const int* in_sizes, int n_in,
                              void* d_out, int out_size) {
    const float* x      = (const float*)d_in[0];
    const int*   src    = (const int*)  d_in[1];
    const int*   dst    = (const int*)  d_in[2];
    const float* self_w = (const float*)d_in[3];
    const float* ppi_w  = (const float*)d_in[4];
    const float* W_in   = (const float*)d_in[5];
    const float* b_in   = (const float*)d_in[6];
    const float* W1     = (const float*)d_in[7];
    const float* b1     = (const float*)d_in[8];
    const float* W2     = (const float*)d_in[9];
    const float* b2     = (const float*)d_in[10];
    const float* W_out  = (const float*)d_in[11];
    const float* b_out  = (const float*)d_in[12];
    float* out = (float*)d_out;

    const int n = in_sizes[0] / DIN;   // 50000
    const int e = in_sizes[1];         // 800000

    float *p_h, *p_h2, *p_agg, *p_res;
    cudaGetSymbolAddress((void**)&p_h,   g_h);
    cudaGetSymbolAddress((void**)&p_h2,  g_h2);
    cudaGetSymbolAddress((void**)&p_agg, g_agg);
    cudaGetSymbolAddress((void**)&p_res, g_res);

    cudaFuncSetAttribute(outgemm_kernel,
                         cudaFuncAttributeMaxDynamicSharedMemorySize, OG_SMEM);

    dim3 gin(1, NNPAD / BM);              // (1, 391)
    int aggBlocks = (n * 32 + 255) / 256;

    // ---- fork: branch B runs wsplit + input GEMM concurrently with CSR ----
    // (captured-stream fork via event dependencies; streams/events created
    //  per host call and not destroyed — host code only runs at correctness
    //  + capture, graph replays don't re-execute it)
    cudaStream_t sB;
    cudaStreamCreate(&sB);
    cudaEvent_t eF, eJ;
    cudaEventCreateWithFlags(&eF, cudaEventDisableTiming);
    cudaEventCreateWithFlags(&eJ, cudaEventDisableTiming);

    cudaEventRecord(eF, 0);
    cudaStreamWaitEvent(sB, eF, 0);
    wsplit_kernel<<<(NL * DH + 255) / 256, 256, 0, sB>>>(W_out);
    sgemm_kernel<<<gin, 256, 0, sB>>>(x, W_in, b_in, nullptr, p_h, n, DH, DIN, 0);
    cudaEventRecord(eJ, sB);

    // ---- main stream: CSR build (deterministic, segments sorted) ----
    const int nb = (n + 1023) / 1024;
    zero_cnt_kernel<<<(n + 255) / 256, 256>>>(n);
    hist_kernel<<<(e + 255) / 256, 256>>>(dst, e);
    scan1_kernel<<<nb, 1024>>>(n);
    scan2_kernel<<<1, 32>>>(nb, n);
    scan3_kernel<<<(n + 255) / 256, 256>>>(n);
    fill_kernel<<<(e + 255) / 256, 256>>>(dst, e);
    segsort_kernel<<<(n + 127) / 128, 128>>>(n);
    permute_kernel<<<(e + 255) / 256, 256>>>(src, ppi_w, self_w, e);

    // ---- join ----
    cudaStreamWaitEvent(0, eJ, 0);

    // layer 1
    agg_kernel<<<aggBlocks, 256>>>(p_h, n);
    sgemm_kernel<<<gin, 256>>>(p_agg, W1, b1, p_res, p_h2, n, DH, DH, 1);

    // layer 2 (epi 3: fused hsplit into epilogue)
    agg_kernel<<<aggBlocks, 256>>>(p_h2, n);
    sgemm_kernel<<<gin, 256>>>(p_agg, W2, b2, p_res, p_h, n, DH, DH, 3);

    // output: pipelined HMMA GEMM (BN=256)
    dim3 gog(NLPAD / HG_BN, NNPAD / HG_BM);              // (4, 391)
    outgemm_kernel<<<gog, 512, OG_SMEM>>>(b_out, out, n);
}